// round 14
// baseline (speedup 1.0000x reference)
#include <cuda_runtime.h>
#include <cuda_fp16.h>
#include <cuda_fp4.h>

// MXFP4 (E2M1) block fake-quant embedding gather — R14:
//   = R13 (3x verified 17.15us) with an 8-elems/thread remap:
//     a 32-elem quant block now spans 4 lanes -> 2 shfl levels (width=4)
//     instead of 8 lanes / 3 levels. Per-thread SHFL count 48 -> 16.
//   All traffic identical: 2 float4 LDGs + 2 float4 STGs per token-slab,
//   warp lanes at 32B stride still cover whole 128B lines.
//   256-thread CTA = 2 tokens in parallel x 8 iterations = 16 tokens/CTA.
// d_in[0]: int32 indices, 16384 tokens
// d_in[1]: float32 embedding table, (50257, 1024)
// d_out  : float32 (16384, 1024)

#define F        1024
#define TOK_CTA  16

__device__ __forceinline__ float2 fp4_pair(float x, float y, float inv) {
    float2 a = make_float2(x * inv, y * inv);
    __nv_fp4x2_storage_t p =
        __nv_cvt_float2_to_fp4x2(a, __NV_E2M1, cudaRoundNearest);
    __half2_raw hr = __nv_cvt_fp4x2_to_halfraw2(p, __NV_E2M1);
    __half2 h = *reinterpret_cast<__half2*>(&hr);
    return __half22float2(h);                      // exact grid values
}

__device__ __forceinline__ float4 maxabs4(float4 v) {
    // |.| of 4 values folded to a single max
    return v;
}

__global__ void __launch_bounds__(256)
mxfp4_embed_kernel(const int* __restrict__ idx,
                   const float* __restrict__ emb,
                   float* __restrict__ out) {
    const int t    = threadIdx.x;
    const int half = t >> 7;                        // which of 2 parallel tokens
    const int lt   = t & 127;                       // lane within token (8 floats each)
    const int base = blockIdx.x * TOK_CTA;

    // vectorized uniform index loads (L1 broadcast): 4x LDG.128
    int rows[TOK_CTA];
    #pragma unroll
    for (int j = 0; j < TOK_CTA / 4; j++) {
        int4 r4 = __ldg(reinterpret_cast<const int4*>(idx + base) + j);
        rows[j * 4 + 0] = r4.x;
        rows[j * 4 + 1] = r4.y;
        rows[j * 4 + 2] = r4.z;
        rows[j * 4 + 3] = r4.w;
    }

    const float4* src = reinterpret_cast<const float4*>(emb);
    float4* outv = reinterpret_cast<float4*>(out);

    #pragma unroll
    for (int it = 0; it < TOK_CTA / 2; it++) {
        const int tok = it * 2 + half;              // token within this CTA
        const int row = rows[tok];

        // this thread's two adjacent float4s (8 consecutive floats of one block)
        const size_t off = (size_t)lt * 2;
        float4 v0 = __ldg(src + (size_t)row * (F / 4) + off);
        float4 v1 = __ldg(src + (size_t)row * (F / 4) + off + 1);

        float m = fmaxf(
            fmaxf(fmaxf(fabsf(v0.x), fabsf(v0.y)), fmaxf(fabsf(v0.z), fabsf(v0.w))),
            fmaxf(fmaxf(fabsf(v1.x), fabsf(v1.y)), fmaxf(fabsf(v1.z), fabsf(v1.w))));

        // 4-lane group max: only 2 shuffle levels
        m = fmaxf(m, __shfl_xor_sync(0xFFFFFFFFu, m, 2, 4));
        m = fmaxf(m, __shfl_xor_sync(0xFFFFFFFFu, m, 1, 4));

        const float sc  = (m == 0.0f) ? 1.0f : m * (1.0f / 6.0f);
        const float inv = (m == 0.0f) ? 0.0f : __fdividef(6.0f, m);

        float2 a0 = fp4_pair(v0.x, v0.y, inv);
        float2 a1 = fp4_pair(v0.z, v0.w, inv);
        float2 b0 = fp4_pair(v1.x, v1.y, inv);
        float2 b1 = fp4_pair(v1.z, v1.w, inv);

        float4 r0, r1;
        r0.x = a0.x * sc;  r0.y = a0.y * sc;
        r0.z = a1.x * sc;  r0.w = a1.y * sc;
        r1.x = b0.x * sc;  r1.y = b0.y * sc;
        r1.z = b1.x * sc;  r1.w = b1.y * sc;

        float4* d = outv + (size_t)(base + tok) * (F / 4) + off;
        __stcs(d,     r0);
        __stcs(d + 1, r1);
    }
}

extern "C" void kernel_launch(void* const* d_in, const int* in_sizes, int n_in,
                              void* d_out, int out_size) {
    const int*   idx = (const int*)d_in[0];
    const float* emb = (const float*)d_in[1];
    float*       out = (float*)d_out;

    const int tokens = in_sizes[0];              // 16384
    mxfp4_embed_kernel<<<tokens / TOK_CTA, 256>>>(idx, emb, out);
}

// round 15
// speedup vs baseline: 1.0782x; 1.0782x over previous
#include <cuda_runtime.h>
#include <cuda_fp16.h>
#include <cuda_fp4.h>

// MXFP4 (E2M1) block fake-quant embedding gather — FINAL (R11/R13, 17.15us x3):
//   - gather + on-the-fly per-32-block fake-quant (never materializes the
//     full dequantized table; only referenced rows are touched)
//   - hardware E2M1 rounding: cvt.rn.satfinite.e2m1x2.f32 via cuda_fp4.h
//   - 4 elems/thread, unit-stride lanes: fully-coalesced LDG.128/STG.128
//     (R14: 8-elem/thread remap doubled L1 wavefronts/LDG -> 27us regression)
//   - 3x shfl.xor width=8 for the 8-lane block max (R10: redux.sync with
//     divergent masks serializes -> 29us regression)
//   - TOK_CTA=16 -> grid=1024: single wave on 148 SMs (R9 win)
//   - st.global.cs streaming stores: clean writeback drain (R8 win)
//   - int4-vectorized index loads
// Converged model: mixed DRAM-write/L2 floor (~68MB compulsory output writes
// at ~3.8 TB/s effective + ~67MB L2-served reads). MLP forcing (asm ordering,
// cp.async), sw pipelining, __ldcg, redux, and layout remaps all measured
// neutral-to-negative across R5-R14.
// d_in[0]: int32 indices, 16384 tokens
// d_in[1]: float32 embedding table, (50257, 1024)
// d_out  : float32 (16384, 1024)

#define F        1024
#define TOK_CTA  16

__device__ __forceinline__ float2 fp4_pair(float x, float y, float inv) {
    float2 a = make_float2(x * inv, y * inv);
    __nv_fp4x2_storage_t p =
        __nv_cvt_float2_to_fp4x2(a, __NV_E2M1, cudaRoundNearest);
    __half2_raw hr = __nv_cvt_fp4x2_to_halfraw2(p, __NV_E2M1);
    __half2 h = *reinterpret_cast<__half2*>(&hr);
    return __half22float2(h);                      // exact grid values
}

__global__ void __launch_bounds__(256)
mxfp4_embed_kernel(const int* __restrict__ idx,
                   const float* __restrict__ emb,
                   float* __restrict__ out) {
    const int t = threadIdx.x;                      // one float4 of a row
    const int base = blockIdx.x * TOK_CTA;

    // vectorized uniform index loads (L1 broadcast): 4x LDG.128
    int rows[TOK_CTA];
    #pragma unroll
    for (int j = 0; j < TOK_CTA / 4; j++) {
        int4 r4 = __ldg(reinterpret_cast<const int4*>(idx + base) + j);
        rows[j * 4 + 0] = r4.x;
        rows[j * 4 + 1] = r4.y;
        rows[j * 4 + 2] = r4.z;
        rows[j * 4 + 3] = r4.w;
    }

    float4* dst = reinterpret_cast<float4*>(out) + (size_t)base * (F / 4) + t;

    #pragma unroll
    for (int j = 0; j < TOK_CTA; j++) {
        float4 v = __ldg(reinterpret_cast<const float4*>(emb) +
                         (size_t)rows[j] * (F / 4) + t);

        // max |.| over this thread's 4 values, then the 8-lane block group
        float m = fmaxf(fmaxf(fabsf(v.x), fabsf(v.y)),
                        fmaxf(fabsf(v.z), fabsf(v.w)));
        #pragma unroll
        for (int o = 4; o > 0; o >>= 1)
            m = fmaxf(m, __shfl_xor_sync(0xFFFFFFFFu, m, o, 8));

        const float sc  = (m == 0.0f) ? 1.0f : m * (1.0f / 6.0f);
        const float inv = (m == 0.0f) ? 0.0f : __fdividef(6.0f, m);

        float2 g0 = fp4_pair(v.x, v.y, inv);
        float2 g1 = fp4_pair(v.z, v.w, inv);

        float4 r;
        r.x = g0.x * sc;
        r.y = g0.y * sc;
        r.z = g1.x * sc;
        r.w = g1.y * sc;

        // streaming store: evict-first, clean writeback drain
        __stcs(dst + (size_t)j * (F / 4), r);
    }
}

extern "C" void kernel_launch(void* const* d_in, const int* in_sizes, int n_in,
                              void* d_out, int out_size) {
    const int*   idx = (const int*)d_in[0];
    const float* emb = (const float*)d_in[1];
    float*       out = (float*)d_out;

    const int tokens = in_sizes[0];              // 16384
    mxfp4_embed_kernel<<<tokens / TOK_CTA, 256>>>(idx, emb, out);
}

// round 16
// speedup vs baseline: 1.5981x; 1.4822x over previous
#include <cuda_runtime.h>
#include <cuda_fp16.h>
#include <cuda_fp4.h>

// MXFP4 (E2M1) block fake-quant embedding gather — FINAL (R11/R13, 17.15us x3).
// R15 measured 25.4us on BYTE-IDENTICAL source with HBM abs throughput down
// 22% (3729 -> 2893 GB/s): environmental (clock/neighbor) variance, not code.
// Re-benching unchanged per rigor.md.
//
//   - gather + on-the-fly per-32-block fake-quant (never materializes the
//     full dequantized table; only referenced rows are touched)
//   - hardware E2M1 rounding: cvt.rn.satfinite.e2m1x2.f32 via cuda_fp4.h
//   - 4 elems/thread, unit-stride lanes: fully-coalesced LDG.128/STG.128
//     (R14: 8-elem/thread remap doubled L1 wavefronts/LDG -> 27us regression)
//   - 3x shfl.xor width=8 for the 8-lane block max (R10: redux.sync with
//     divergent masks serializes -> 29us regression)
//   - TOK_CTA=16 -> grid=1024: single wave on 148 SMs (R9 win)
//   - st.global.cs streaming stores: clean writeback drain (R8 win)
//   - int4-vectorized index loads
// Converged model: mixed DRAM-write/L2 floor (~68MB compulsory output writes
// at ~3.8 TB/s effective + ~67MB L2-served reads). MLP forcing (asm ordering,
// cp.async), sw pipelining, __ldcg, redux, and layout remaps all measured
// neutral-to-negative across R5-R14.
// d_in[0]: int32 indices, 16384 tokens
// d_in[1]: float32 embedding table, (50257, 1024)
// d_out  : float32 (16384, 1024)

#define F        1024
#define TOK_CTA  16

__device__ __forceinline__ float2 fp4_pair(float x, float y, float inv) {
    float2 a = make_float2(x * inv, y * inv);
    __nv_fp4x2_storage_t p =
        __nv_cvt_float2_to_fp4x2(a, __NV_E2M1, cudaRoundNearest);
    __half2_raw hr = __nv_cvt_fp4x2_to_halfraw2(p, __NV_E2M1);
    __half2 h = *reinterpret_cast<__half2*>(&hr);
    return __half22float2(h);                      // exact grid values
}

__global__ void __launch_bounds__(256)
mxfp4_embed_kernel(const int* __restrict__ idx,
                   const float* __restrict__ emb,
                   float* __restrict__ out) {
    const int t = threadIdx.x;                      // one float4 of a row
    const int base = blockIdx.x * TOK_CTA;

    // vectorized uniform index loads (L1 broadcast): 4x LDG.128
    int rows[TOK_CTA];
    #pragma unroll
    for (int j = 0; j < TOK_CTA / 4; j++) {
        int4 r4 = __ldg(reinterpret_cast<const int4*>(idx + base) + j);
        rows[j * 4 + 0] = r4.x;
        rows[j * 4 + 1] = r4.y;
        rows[j * 4 + 2] = r4.z;
        rows[j * 4 + 3] = r4.w;
    }

    float4* dst = reinterpret_cast<float4*>(out) + (size_t)base * (F / 4) + t;

    #pragma unroll
    for (int j = 0; j < TOK_CTA; j++) {
        float4 v = __ldg(reinterpret_cast<const float4*>(emb) +
                         (size_t)rows[j] * (F / 4) + t);

        // max |.| over this thread's 4 values, then the 8-lane block group
        float m = fmaxf(fmaxf(fabsf(v.x), fabsf(v.y)),
                        fmaxf(fabsf(v.z), fabsf(v.w)));
        #pragma unroll
        for (int o = 4; o > 0; o >>= 1)
            m = fmaxf(m, __shfl_xor_sync(0xFFFFFFFFu, m, o, 8));

        const float sc  = (m == 0.0f) ? 1.0f : m * (1.0f / 6.0f);
        const float inv = (m == 0.0f) ? 0.0f : __fdividef(6.0f, m);

        float2 g0 = fp4_pair(v.x, v.y, inv);
        float2 g1 = fp4_pair(v.z, v.w, inv);

        float4 r;
        r.x = g0.x * sc;
        r.y = g0.y * sc;
        r.z = g1.x * sc;
        r.w = g1.y * sc;

        // streaming store: evict-first, clean writeback drain
        __stcs(dst + (size_t)j * (F / 4), r);
    }
}

extern "C" void kernel_launch(void* const* d_in, const int* in_sizes, int n_in,
                              void* d_out, int out_size) {
    const int*   idx = (const int*)d_in[0];
    const float* emb = (const float*)d_in[1];
    float*       out = (float*)d_out;

    const int tokens = in_sizes[0];              // 16384
    mxfp4_embed_kernel<<<tokens / TOK_CTA, 256>>>(idx, emb, out);
}